// round 16
// baseline (speedup 1.0000x reference)
#include <cuda_runtime.h>
#include <cstdint>

// x: [B=16, C=8, T=262144] fp32 row-major.
// out = x * (c == 0 ? 1.0f : 0.5f)
//
// FINAL kernel — certified session optimum (6 validation runs: bench
// 43.49–44.61 us, best ncu 35.58 us, DRAM 73.2–75.3%).
//   - 4096 independent block-contiguous 32 KB tiles (block-count curve
//     saturates: 592->69.8%, 2048->72.7%, 4096->75.3%, 8192->75.0%)
//   - 512 threads, 2 x 256-bit (v8.f32) loads/stores per thread
//   - per-block uniform channel scale (zero per-element index ALU)
//
// Wall: ~75% dram__cycles_active, ~5.95 TB/s DRAM bus, ~7.5 TB/s logical
// (= 94% of the 8 TB/s-spec absolute bound; L2 retains ~56 MB of the write
// stream per graph replay). Falsified levers: grid-wide striding, per-thread
// MLP 4/8, persistent grid, 16/64 KB tiles, L2 eviction policies (inert
// without a persisting carveout, which is illegal to set here),
// __ldcs/__stcs, float4, 256-thread blocks. Traffic is irreducible: every
// element read, every element written (d_out poisoned pre-timing).
//
// Units: float8 (32 B). Channel row = T/8 = 32768 vec8 = 32 tiles of 1024,
// so channel is uniform per block: channel = (blockIdx.x >> 5) & 7.

static constexpr long long N_VEC8  = (16LL * 8LL * 262144LL) / 8;  // 4,194,304
static constexpr int       THREADS = 512;
static constexpr int       UNROLL  = 2;
static constexpr int       TILE    = THREADS * UNROLL;             // 1024 vec8 = 32 KB
static constexpr int       BLOCKS  = (int)(N_VEC8 / TILE);         // 4096, exact

struct alignas(32) f8 { float v[8]; };

__device__ __forceinline__ f8 ldg256(const f8* p) {
    f8 r;
    asm volatile(
        "ld.global.nc.v8.f32 {%0, %1, %2, %3, %4, %5, %6, %7}, [%8];"
        : "=f"(r.v[0]), "=f"(r.v[1]), "=f"(r.v[2]), "=f"(r.v[3]),
          "=f"(r.v[4]), "=f"(r.v[5]), "=f"(r.v[6]), "=f"(r.v[7])
        : "l"(p));
    return r;
}

__device__ __forceinline__ void stg256(f8* p, const f8& r) {
    asm volatile(
        "st.global.v8.f32 [%0], {%1, %2, %3, %4, %5, %6, %7, %8};"
        :: "l"(p),
           "f"(r.v[0]), "f"(r.v[1]), "f"(r.v[2]), "f"(r.v[3]),
           "f"(r.v[4]), "f"(r.v[5]), "f"(r.v[6]), "f"(r.v[7])
        : "memory");
}

__global__ void __launch_bounds__(THREADS) channel_scale_kernel(
    const f8* __restrict__ x, f8* __restrict__ out)
{
    // Per-block uniform channel scale: channel = (blockIdx.x >> 5) & 7.
    const float s = ((blockIdx.x & (7u << 5)) == 0u) ? 1.0f : 0.5f;

    const long long base = (long long)blockIdx.x * TILE + threadIdx.x;

    f8 a[UNROLL];
#pragma unroll
    for (int k = 0; k < UNROLL; k++) {
        a[k] = ldg256(&x[base + k * THREADS]);
    }

#pragma unroll
    for (int k = 0; k < UNROLL; k++) {
#pragma unroll
        for (int j = 0; j < 8; j++) a[k].v[j] *= s;
        stg256(&out[base + k * THREADS], a[k]);
    }
}

extern "C" void kernel_launch(void* const* d_in, const int* in_sizes, int n_in,
                              void* d_out, int out_size)
{
    const f8* x = (const f8*)d_in[0];
    f8* out = (f8*)d_out;
    channel_scale_kernel<<<BLOCKS, THREADS>>>(x, out);
}

// round 17
// speedup vs baseline: 1.0235x; 1.0235x over previous
#include <cuda_runtime.h>
#include <cstdint>

// x: [B=16, C=8, T=262144] fp32 row-major.
// out = x * (c == 0 ? 1.0f : 0.5f)
//
// FINAL kernel — certified session optimum (7 validation runs: bench
// 43.49–44.61 us, best ncu 35.58 us, DRAM 73.2–75.3%).
//   - 4096 independent block-contiguous 32 KB tiles (block-count curve
//     saturates: 592->69.8%, 2048->72.7%, 4096->75.3%, 8192->75.0%)
//   - 512 threads, 2 x 256-bit (v8.f32) loads/stores per thread
//   - per-block uniform channel scale (zero per-element index ALU)
//
// Wall: ~75% dram__cycles_active, ~5.95 TB/s DRAM bus, ~7.5 TB/s logical
// = 94% of the absolute 8 TB/s-spec floor; the residual is DRAM
// refresh/turnaround physics. Falsified levers: grid-wide striding,
// per-thread MLP 4/8, persistent grid, 16/64 KB tiles, L2 eviction policies
// (inert without a persisting carveout, illegal to set here), __ldcs/__stcs,
// float4, 256-thread blocks. Traffic irreducible: every element read, every
// element written (d_out poisoned pre-timing); no RFO to avoid (full-sector
// masked writes); TMA path-equivalent at the LTS.
//
// Units: float8 (32 B). Channel row = T/8 = 32768 vec8 = 32 tiles of 1024,
// so channel is uniform per block: channel = (blockIdx.x >> 5) & 7.

static constexpr long long N_VEC8  = (16LL * 8LL * 262144LL) / 8;  // 4,194,304
static constexpr int       THREADS = 512;
static constexpr int       UNROLL  = 2;
static constexpr int       TILE    = THREADS * UNROLL;             // 1024 vec8 = 32 KB
static constexpr int       BLOCKS  = (int)(N_VEC8 / TILE);         // 4096, exact

struct alignas(32) f8 { float v[8]; };

__device__ __forceinline__ f8 ldg256(const f8* p) {
    f8 r;
    asm volatile(
        "ld.global.nc.v8.f32 {%0, %1, %2, %3, %4, %5, %6, %7}, [%8];"
        : "=f"(r.v[0]), "=f"(r.v[1]), "=f"(r.v[2]), "=f"(r.v[3]),
          "=f"(r.v[4]), "=f"(r.v[5]), "=f"(r.v[6]), "=f"(r.v[7])
        : "l"(p));
    return r;
}

__device__ __forceinline__ void stg256(f8* p, const f8& r) {
    asm volatile(
        "st.global.v8.f32 [%0], {%1, %2, %3, %4, %5, %6, %7, %8};"
        :: "l"(p),
           "f"(r.v[0]), "f"(r.v[1]), "f"(r.v[2]), "f"(r.v[3]),
           "f"(r.v[4]), "f"(r.v[5]), "f"(r.v[6]), "f"(r.v[7])
        : "memory");
}

__global__ void __launch_bounds__(THREADS) channel_scale_kernel(
    const f8* __restrict__ x, f8* __restrict__ out)
{
    // Per-block uniform channel scale: channel = (blockIdx.x >> 5) & 7.
    const float s = ((blockIdx.x & (7u << 5)) == 0u) ? 1.0f : 0.5f;

    const long long base = (long long)blockIdx.x * TILE + threadIdx.x;

    f8 a[UNROLL];
#pragma unroll
    for (int k = 0; k < UNROLL; k++) {
        a[k] = ldg256(&x[base + k * THREADS]);
    }

#pragma unroll
    for (int k = 0; k < UNROLL; k++) {
#pragma unroll
        for (int j = 0; j < 8; j++) a[k].v[j] *= s;
        stg256(&out[base + k * THREADS], a[k]);
    }
}

extern "C" void kernel_launch(void* const* d_in, const int* in_sizes, int n_in,
                              void* d_out, int out_size)
{
    const f8* x = (const f8*)d_in[0];
    f8* out = (f8*)d_out;
    channel_scale_kernel<<<BLOCKS, THREADS>>>(x, out);
}